// round 14
// baseline (speedup 1.0000x reference)
#include <cuda_runtime.h>
#include <cuda_fp16.h>
#include <cmath>
#include <cstdint>

#define NLINK 2000
#define NFLOW 30000
#define NPATH 50000
#define E1N   120000
#define E2N   120000
#define HIDN  256
#define NH    4
#define HD    256

// ---------------- scratch ----------------
__device__ __half g_h_link[NLINK * HIDN];
__device__ __half g_h_flow[NFLOW * HIDN];
__device__ __half g_h_path0[NPATH * HIDN];
__device__ __half g_h_path1[NPATH * HIDN];
__device__ __half g_h_path2[NPATH * HIDN];
__device__ __half g_zs1[NLINK * NH * HD];
__device__ __half g_zs2[NFLOW * NH * HD];
__device__ __half g_hidden[NPATH * HIDN];
__device__ float  g_el1[NLINK * NH];
__device__ float  g_er1[NPATH * NH];
__device__ float  g_el2[NFLOW * NH];
__device__ float  g_er2[NPATH * NH];
__device__ float  g_ea[E1N * NH];
__device__ float  g_denom[NPATH * NH];
__device__ float  g_agg[NPATH * HIDN];
__device__ float  g_wl1[HIDN * NH];
__device__ float  g_wr1[HIDN * NH];
__device__ float  g_wl2[HIDN * NH];
__device__ float  g_wr2[HIDN * NH];
__device__ float  g_ce[NH];
// fp16 transposed weights [N][K]
__device__ __half g_fc1t[NH * HD * HIDN];
__device__ __half g_fc2t[NH * HD * HIDN];
__device__ __half g_rw1t[HIDN * HIDN];
__device__ __half g_rw2t[HIDN * HIDN];
__device__ __half g_wcatT[HIDN * 2 * HIDN];

// ---------------- helpers ----------------
__device__ __forceinline__ void mma_f16(float* c, const uint32_t* a, const uint32_t* b) {
    asm volatile(
        "mma.sync.aligned.m16n8k16.row.col.f32.f16.f16.f32 "
        "{%0,%1,%2,%3}, {%4,%5,%6,%7}, {%8,%9}, {%0,%1,%2,%3};"
        : "+f"(c[0]), "+f"(c[1]), "+f"(c[2]), "+f"(c[3])
        : "r"(a[0]), "r"(a[1]), "r"(a[2]), "r"(a[3]), "r"(b[0]), "r"(b[1]));
}

__device__ __forceinline__ void ldsm_x4(uint32_t& r0, uint32_t& r1, uint32_t& r2,
                                        uint32_t& r3, uint32_t saddr) {
    asm volatile("ldmatrix.sync.aligned.m8n8.x4.shared.b16 {%0,%1,%2,%3}, [%4];"
                 : "=r"(r0), "=r"(r1), "=r"(r2), "=r"(r3) : "r"(saddr));
}

__device__ __forceinline__ void cp16(uint32_t saddr, const void* gaddr, int szbytes) {
    asm volatile("cp.async.cg.shared.global [%0], [%1], 16, %2;\n"
                 :: "r"(saddr), "l"(gaddr), "r"(szbytes));
}
__device__ __forceinline__ void cp_commit() { asm volatile("cp.async.commit_group;\n"); }
template <int W>
__device__ __forceinline__ void cp_wait() { asm volatile("cp.async.wait_group %0;\n" :: "n"(W)); }

__global__ void fill_conv_state(float* __restrict__ denom, float* __restrict__ agg) {
    int i = blockIdx.x * blockDim.x + threadIdx.x;
    if (i < NPATH * NH) denom[i] = 0.0f;
    if (i < NPATH * HIDN) agg[i] = 0.0f;
}

// transpose + fp16-convert all GEMM weights; fold W1 concat
__global__ void prep_weights(const float* __restrict__ fc1, const float* __restrict__ fc2,
                             const float* __restrict__ rw1, const float* __restrict__ rw2,
                             const float* __restrict__ W1,
                             __half* __restrict__ fc1t, __half* __restrict__ fc2t,
                             __half* __restrict__ rw1t, __half* __restrict__ rw2t,
                             __half* __restrict__ wcatT) {
    int i = blockIdx.x * blockDim.x + threadIdx.x;
    const int NFC = 1024 * 256, NRW = 256 * 256;
    if (i < NFC) {
        int n = i >> 8, k = i & 255;
        fc1t[i] = __float2half_rn(fc1[k * 1024 + n]);
        fc2t[i] = __float2half_rn(fc2[k * 1024 + n]);
    }
    if (i < NRW) {
        int n = i >> 8, k = i & 255;
        rw1t[i] = __float2half_rn(rw1[k * 256 + n]);
        rw2t[i] = __float2half_rn(rw2[k * 256 + n]);
    }
    if (i < 256 * 512) {
        int n = i >> 9, k = i & 511;
        float v = W1[k * 256 + n];
        if (k < 256) v += W1[(k + 512) * 256 + n];
        wcatT[i] = __float2half_rn(v);
    }
}

// ---------------- proj_relu ----------------
template <int KIN>
__global__ __launch_bounds__(256)
void proj_relu(const float* __restrict__ x, const float* __restrict__ W,
               const float* __restrict__ b, __half* __restrict__ out, int M) {
    __shared__ float xs[32][KIN];
    const int c = threadIdx.x;
    const int row0 = blockIdx.x * 32;
    for (int i = c; i < 32 * KIN; i += 256) {
        int r = i / KIN, k = i % KIN;
        xs[r][k] = (row0 + r < M) ? x[(size_t)(row0 + r) * KIN + k] : 0.0f;
    }
    float w[KIN];
#pragma unroll
    for (int k = 0; k < KIN; ++k) w[k] = W[k * HIDN + c];
    const float bias = b[c];
    __syncthreads();
    int rmax = min(32, M - row0);
    for (int r = 0; r < rmax; ++r) {
        float s = bias;
#pragma unroll
        for (int k = 0; k < KIN; ++k) s += xs[r][k] * w[k];
        out[(size_t)(row0 + r) * HIDN + c] = __float2half_rn(fmaxf(s, 0.0f));
    }
}

// one warp per output; 0..4095: wl1/wr1/wl2/wr2; 4096..4099: ce
__global__ void attn_reduce_all(
    const float* __restrict__ fcA, const float* __restrict__ aA, float* __restrict__ oA,
    const float* __restrict__ fcB, const float* __restrict__ aB, float* __restrict__ oB,
    const float* __restrict__ fcC, const float* __restrict__ aC, float* __restrict__ oC,
    const float* __restrict__ fcD, const float* __restrict__ aD, float* __restrict__ oD,
    const float* __restrict__ fcE, const float* __restrict__ aE, float* __restrict__ oE) {
    int gw = (blockIdx.x * blockDim.x + threadIdx.x) >> 5;
    int lane = threadIdx.x & 31;
    if (gw >= 4100) return;
    const float *fc, *at; float* out; int foff, aoff, oidx;
    if (gw < 4096) {
        int sel = gw >> 10, t = gw & 1023;
        int k = t >> 2, h = t & 3;
        switch (sel) {
            case 0: fc = fcA; at = aA; out = oA; break;
            case 1: fc = fcB; at = aB; out = oB; break;
            case 2: fc = fcC; at = aC; out = oC; break;
            default: fc = fcD; at = aD; out = oD; break;
        }
        foff = k * (NH * HD) + h * HD; aoff = h * HD; oidx = t;
    } else {
        int h = gw - 4096;
        fc = fcE; at = aE; out = oE;
        foff = h * HD; aoff = h * HD; oidx = h;
    }
    float s = 0.0f;
    for (int d = lane; d < HD; d += 32) s += fc[foff + d] * at[aoff + d];
#pragma unroll
    for (int o = 16; o > 0; o >>= 1) s += __shfl_down_sync(0xffffffffu, s, o);
    if (lane == 0) out[oidx] = s;
}

// ---------------- attn scores ----------------
__device__ __forceinline__ void attn_dot_store(const __half* __restrict__ row,
                                               const float* __restrict__ w,
                                               float* __restrict__ out, int lane) {
    float s0 = 0.f, s1 = 0.f, s2 = 0.f, s3 = 0.f;
    const __half2* r2 = (const __half2*)row;
#pragma unroll
    for (int j = 0; j < 4; ++j) {
        int i2 = lane + 32 * j;
        float2 f = __half22float2(r2[i2]);
        int k = 2 * i2;
        float4 w0 = *(const float4*)(w + 4 * k);
        float4 w1 = *(const float4*)(w + 4 * k + 4);
        s0 += f.x * w0.x + f.y * w1.x;
        s1 += f.x * w0.y + f.y * w1.y;
        s2 += f.x * w0.z + f.y * w1.z;
        s3 += f.x * w0.w + f.y * w1.w;
    }
#pragma unroll
    for (int o = 16; o > 0; o >>= 1) {
        s0 += __shfl_down_sync(0xffffffffu, s0, o);
        s1 += __shfl_down_sync(0xffffffffu, s1, o);
        s2 += __shfl_down_sync(0xffffffffu, s2, o);
        s3 += __shfl_down_sync(0xffffffffu, s3, o);
    }
    if (lane == 0) *(float4*)out = make_float4(s0, s1, s2, s3);
}

__global__ void attn_score3(const __half* __restrict__ hlink, const __half* __restrict__ hflow,
                            const __half* __restrict__ hpath,
                            const float* __restrict__ wl1, const float* __restrict__ wl2,
                            const float* __restrict__ wr1,
                            float* __restrict__ el1, float* __restrict__ el2,
                            float* __restrict__ er1) {
    int gw = (blockIdx.x * blockDim.x + threadIdx.x) >> 5;
    int lane = threadIdx.x & 31;
    if (gw >= NLINK + NFLOW + NPATH) return;
    const __half* row; const float* w; float* out;
    if (gw < NLINK)               { row = hlink + (size_t)gw * HIDN; w = wl1; out = el1 + gw * 4; }
    else if (gw < NLINK + NFLOW)  { int r = gw - NLINK; row = hflow + (size_t)r * HIDN; w = wl2; out = el2 + r * 4; }
    else                          { int r = gw - NLINK - NFLOW; row = hpath + (size_t)r * HIDN; w = wr1; out = er1 + r * 4; }
    attn_dot_store(row, w, out, lane);
}

__global__ void attn_score1(const __half* __restrict__ hfeat, const float* __restrict__ w,
                            float* __restrict__ out, int M) {
    int gw = (blockIdx.x * blockDim.x + threadIdx.x) >> 5;
    int lane = threadIdx.x & 31;
    if (gw >= M) return;
    attn_dot_store(hfeat + (size_t)gw * HIDN, w, out + gw * 4, lane);
}

// ---------------- fused edge softmax ----------------
template <bool HAS_EE>
__global__ void edge_softmax(const float* __restrict__ el, const float* __restrict__ er,
                             const float* __restrict__ ef, const float* __restrict__ ce,
                             const int* __restrict__ src, const int* __restrict__ dst,
                             float* __restrict__ a_out, float* __restrict__ denom, int E) {
    int e = blockIdx.x * blockDim.x + threadIdx.x;
    if (e >= E) return;
    int s = src[e], d = dst[e];
    float4 a = *(const float4*)(el + s * 4);
    float4 b = *(const float4*)(er + d * 4);
    float v[4] = { a.x + b.x, a.y + b.y, a.z + b.z, a.w + b.w };
    if (HAS_EE) {
        float f = ef[e];
        float4 c = *(const float4*)ce;
        v[0] += f * c.x; v[1] += f * c.y; v[2] += f * c.z; v[3] += f * c.w;
    }
#pragma unroll
    for (int h = 0; h < 4; ++h) {
        float lv = v[h] > 0.0f ? v[h] : 0.2f * v[h];
        v[h] = __expf(lv);
    }
    *(float4*)(a_out + e * 4) = make_float4(v[0], v[1], v[2], v[3]);
    atomicAdd(&denom[d * 4 + 0], v[0]);
    atomicAdd(&denom[d * 4 + 1], v[1]);
    atomicAdd(&denom[d * 4 + 2], v[2]);
    atomicAdd(&denom[d * 4 + 3], v[3]);
}

// ---------------- edge scatter: 8 edges per 512-thread block ----------------
__global__ __launch_bounds__(512)
void edge_scatter(const __half* __restrict__ zs, const float* __restrict__ a_in,
                  const float* __restrict__ denom,
                  const int* __restrict__ src, const int* __restrict__ dst,
                  float* __restrict__ agg, int E) {
    int e = blockIdx.x * 8 + (threadIdx.x >> 6);
    if (e >= E) return;
    int t = threadIdx.x & 63;
    int s = src[e], d = dst[e];
    float al[NH];
    float4 av = *(const float4*)(a_in + e * 4);
    float4 dv = *(const float4*)(denom + d * 4);
    al[0] = 0.25f * av.x / fmaxf(dv.x, 1e-9f);
    al[1] = 0.25f * av.y / fmaxf(dv.y, 1e-9f);
    al[2] = 0.25f * av.z / fmaxf(dv.z, 1e-9f);
    al[3] = 0.25f * av.w / fmaxf(dv.w, 1e-9f);
    const uint2* z = (const uint2*)(zs + (size_t)s * (NH * HD));
    float4 r = make_float4(0.f, 0.f, 0.f, 0.f);
#pragma unroll
    for (int h = 0; h < NH; ++h) {
        uint2 u = __ldg(&z[h * 64 + t]);
        float2 f0 = __half22float2(*(const __half2*)&u.x);
        float2 f1 = __half22float2(*(const __half2*)&u.y);
        r.x += al[h] * f0.x; r.y += al[h] * f0.y;
        r.z += al[h] * f1.x; r.w += al[h] * f1.y;
    }
    float* outp = agg + (size_t)d * HIDN + t * 4;
    asm volatile("red.global.add.v4.f32 [%0], {%1,%2,%3,%4};"
                 :: "l"(outp), "f"(r.x), "f"(r.y), "f"(r.z), "f"(r.w) : "memory");
}

__global__ void decoder_out(const __half* __restrict__ hidden, const float* __restrict__ W2,
                            const float* __restrict__ b2, float* __restrict__ out) {
    int gw = (blockIdx.x * blockDim.x + threadIdx.x) >> 5;
    int lane = threadIdx.x & 31;
    if (gw >= NPATH) return;
    const __half2* hrow = (const __half2*)(hidden + (size_t)gw * HIDN);
    float s0 = 0.f, s1 = 0.f;
#pragma unroll
    for (int j = 0; j < 4; ++j) {
        int i2 = lane + 32 * j;
        float2 f = __half22float2(hrow[i2]);
        int k = 2 * i2;
        float2 w0 = *(const float2*)(W2 + 2 * k);
        float2 w1 = *(const float2*)(W2 + 2 * k + 2);
        s0 += f.x * w0.x + f.y * w1.x;
        s1 += f.x * w0.y + f.y * w1.y;
    }
#pragma unroll
    for (int o = 16; o > 0; o >>= 1) {
        s0 += __shfl_down_sync(0xffffffffu, s0, o);
        s1 += __shfl_down_sync(0xffffffffu, s1, o);
    }
    if (lane == 0) *(float2*)(out + gw * 2) = make_float2(s0 + b2[0], s1 + b2[1]);
}

// ---------------- fp16 tensor-core GEMM, wide tiles ----------------
// C[M,N] = epi(A[M,K] @ Bt[N,K]^T). Block 128x256, 8 warps (2x4) of 64x64, BK=32.
// 3-stage cp.async pipeline; smem rows padded to 40 halves (80B) -> LDSM conflict-free.
// EPI: 1 = fp16 out, 2 = relu(+add[M,N]) fp16, 3 = relu(+bias[N]) fp16.
// SPLITA: A col k<256 from A, else A2 (fused concat; both row stride 256).
#define MM_STAGES 3
#define MM_TA_U32 (128 * 20)
#define MM_TB_U32 (256 * 20)
#define MM_SMEM_BYTES (MM_STAGES * (MM_TA_U32 + MM_TB_U32) * 4)
template <int EPI, bool SPLITA>
__global__ __launch_bounds__(256, 1)
void mm_f16(const __half* __restrict__ A, const __half* __restrict__ A2,
            const __half* __restrict__ Bt, void* __restrict__ Cout,
            int M, int N, int K,
            const float* __restrict__ add, const float* __restrict__ bias) {
    extern __shared__ uint32_t smem[];
    uint32_t* AsB = smem;                                  // [ST][128][20]
    uint32_t* BsB = smem + MM_STAGES * MM_TA_U32;          // [ST][256][20]
    const int tid = threadIdx.x;
    const int lane = tid & 31, wid = tid >> 5;
    const int g = lane >> 2, tig = lane & 3;
    const int warp_m = (wid >> 2) * 64, warp_n = (wid & 3) * 64;
    const int row0 = blockIdx.y * 128, col0 = blockIdx.x * 256;

    float acc[4][8][4];
#pragma unroll
    for (int i = 0; i < 4; ++i)
#pragma unroll
        for (int j = 0; j < 8; ++j)
#pragma unroll
            for (int r = 0; r < 4; ++r) acc[i][j][r] = 0.0f;

    auto issue = [&](int st, int k0) {
        // A: 128 rows x 4 chunks (512 total, 2/thread)
#pragma unroll
        for (int p = 0; p < 2; ++p) {
            int q = tid + 256 * p;
            int row = q >> 2, cik = q & 3;
            int c = k0 + cik * 8;
            int r = row0 + row;
            const __half* asrc = A;
            int sz = 0;
            if (r < M) {
                sz = 16;
                if (SPLITA) asrc = (c < HIDN) ? (A + (size_t)r * HIDN + c)
                                              : (A2 + (size_t)r * HIDN + (c - HIDN));
                else        asrc = A + (size_t)r * K + c;
            }
            cp16((uint32_t)__cvta_generic_to_shared(AsB + st * MM_TA_U32 + row * 20 + cik * 4),
                 asrc, sz);
        }
        // B: 256 rows x 4 chunks (1024 total, 4/thread)
#pragma unroll
        for (int p = 0; p < 4; ++p) {
            int q = tid + 256 * p;
            int row = q >> 2, cik = q & 3;
            int c = k0 + cik * 8;
            const __half* bsrc = Bt + (size_t)(col0 + row) * K + c;
            cp16((uint32_t)__cvta_generic_to_shared(BsB + st * MM_TB_U32 + row * 20 + cik * 4),
                 bsrc, 16);
        }
        cp_commit();
    };

    // ldmatrix lane-address components (bytes)
    const uint32_t a_lane_off = ((lane & 7) + 8 * ((lane >> 3) & 1)) * 80 + 16 * (lane >> 4);
    const uint32_t b_lane_off = ((lane & 7) + 8 * (lane >> 4)) * 80 + 16 * ((lane >> 3) & 1);

    const int nIter = K / 32;
    issue(0, 0);
    issue(1, 32);
    for (int it = 0; it < nIter; ++it) {
        if (it == nIter - 1) cp_wait<0>(); else cp_wait<1>();
        __syncthreads();
        if (it + 2 < nIter) issue((it + 2) % MM_STAGES, (it + 2) * 32);
        const uint32_t As_byte =
            (uint32_t)__cvta_generic_to_shared(AsB + (it % MM_STAGES) * MM_TA_U32);
        const uint32_t Bs_byte =
            (uint32_t)__cvta_generic_to_shared(BsB + (it % MM_STAGES) * MM_TB_U32);
#pragma unroll
        for (int ks = 0; ks < 2; ++ks) {
            uint32_t af[4][4], bf[8][2];
#pragma unroll
            for (int mi = 0; mi < 4; ++mi)
                ldsm_x4(af[mi][0], af[mi][1], af[mi][2], af[mi][3],
                        As_byte + (warp_m + 16 * mi) * 80 + ks * 32 + a_lane_off);
#pragma unroll
            for (int np = 0; np < 4; ++np)
                ldsm_x4(bf[2 * np][0], bf[2 * np][1], bf[2 * np + 1][0], bf[2 * np + 1][1],
                        Bs_byte + (warp_n + 16 * np) * 80 + ks * 32 + b_lane_off);
#pragma unroll
            for (int mi = 0; mi < 4; ++mi)
#pragma unroll
                for (int ni = 0; ni < 8; ++ni)
                    mma_f16(acc[mi][ni], af[mi], bf[ni]);
        }
    }

#pragma unroll
    for (int mi = 0; mi < 4; ++mi) {
#pragma unroll
        for (int ni = 0; ni < 8; ++ni) {
            int rA = row0 + warp_m + 16 * mi + g;
            int cA = col0 + warp_n + 8 * ni + 2 * tig;
#pragma unroll
            for (int half_ = 0; half_ < 2; ++half_) {
                int r = rA + half_ * 8;
                if (r >= M) continue;
                float v0 = acc[mi][ni][half_ * 2 + 0];
                float v1 = acc[mi][ni][half_ * 2 + 1];
                if (EPI == 2) {
                    v0 = fmaxf(v0 + add[(size_t)r * N + cA + 0], 0.0f);
                    v1 = fmaxf(v1 + add[(size_t)r * N + cA + 1], 0.0f);
                } else if (EPI == 3) {
                    v0 = fmaxf(v0 + bias[cA + 0], 0.0f);
                    v1 = fmaxf(v1 + bias[cA + 1], 0.0f);
                }
                __half2* C = (__half2*)Cout;
                C[((size_t)r * N + cA) >> 1] = __floats2half2_rn(v0, v1);
            }
        }
    }
}

// ---------------- host launch ----------------
static inline int cdiv(int a, int b) { return (a + b - 1) / b; }

extern "C" void kernel_launch(void* const* d_in, const int* in_sizes, int n_in,
                              void* d_out, int out_size) {
    (void)in_sizes; (void)n_in; (void)out_size;
    const float* x_link  = (const float*)d_in[0];
    const float* x_flow  = (const float*)d_in[1];
    const float* x_path  = (const float*)d_in[2];
    const float* e2p     = (const float*)d_in[3];
    const float* Wp_link = (const float*)d_in[4];
    const float* bp_link = (const float*)d_in[5];
    const float* Wp_flow = (const float*)d_in[6];
    const float* bp_flow = (const float*)d_in[7];
    const float* Wp_path = (const float*)d_in[8];
    const float* bp_path = (const float*)d_in[9];
    const float* fc_src1 = (const float*)d_in[10];
    const float* fc_dst1 = (const float*)d_in[11];
    const float* fc_e1   = (const float*)d_in[12];
    const float* attn_l1 = (const float*)d_in[13];
    const float* attn_r1 = (const float*)d_in[14];
    const float* attn_e1 = (const float*)d_in[15];
    const float* res_W1  = (const float*)d_in[16];
    const float* fc_src2 = (const float*)d_in[17];
    const float* fc_dst2 = (const float*)d_in[18];
    const float* attn_l2 = (const float*)d_in[19];
    const float* attn_r2 = (const float*)d_in[20];
    const float* res_W2  = (const float*)d_in[21];
    const float* W1      = (const float*)d_in[22];
    const float* b1      = (const float*)d_in[23];
    const float* W2      = (const float*)d_in[24];
    const float* b2      = (const float*)d_in[25];
    const int*   src1    = (const int*)d_in[26];
    const int*   dst1    = (const int*)d_in[27];
    const int*   src2    = (const int*)d_in[28];
    const int*   dst2    = (const int*)d_in[29];
    float* out = (float*)d_out;

#define SYMF(p, s) float* p; cudaGetSymbolAddress((void**)&p, s)
#define SYMH(p, s) __half* p; cudaGetSymbolAddress((void**)&p, s)
    SYMH(p_hlink, g_h_link);  SYMH(p_hflow, g_h_flow);
    SYMH(p_hp0, g_h_path0);   SYMH(p_hp1, g_h_path1);   SYMH(p_hp2, g_h_path2);
    SYMH(p_zs1, g_zs1);       SYMH(p_zs2, g_zs2);       SYMH(p_hidden, g_hidden);
    SYMF(p_el1, g_el1);       SYMF(p_er1, g_er1);
    SYMF(p_el2, g_el2);       SYMF(p_er2, g_er2);
    SYMF(p_ea, g_ea);         SYMF(p_denom, g_denom);   SYMF(p_agg, g_agg);
    SYMF(p_wl1, g_wl1);       SYMF(p_wr1, g_wr1);
    SYMF(p_wl2, g_wl2);       SYMF(p_wr2, g_wr2);       SYMF(p_ce, g_ce);
    SYMH(p_fc1t, g_fc1t);     SYMH(p_fc2t, g_fc2t);
    SYMH(p_rw1t, g_rw1t);     SYMH(p_rw2t, g_rw2t);     SYMH(p_wcatT, g_wcatT);
#undef SYMF
#undef SYMH

    const int T = 256;

    cudaFuncSetAttribute(mm_f16<1, false>, cudaFuncAttributeMaxDynamicSharedMemorySize, MM_SMEM_BYTES);
    cudaFuncSetAttribute(mm_f16<2, false>, cudaFuncAttributeMaxDynamicSharedMemorySize, MM_SMEM_BYTES);
    cudaFuncSetAttribute(mm_f16<3, true>,  cudaFuncAttributeMaxDynamicSharedMemorySize, MM_SMEM_BYTES);

    // --- weight prep ---
    attn_reduce_all<<<cdiv(4100 * 32, T), T>>>(
        fc_src1, attn_l1, p_wl1,  fc_dst1, attn_r1, p_wr1,
        fc_src2, attn_l2, p_wl2,  fc_dst2, attn_r2, p_wr2,
        fc_e1, attn_e1, p_ce);
    prep_weights<<<cdiv(1024 * 256, T), T>>>(fc_src1, fc_src2, res_W1, res_W2, W1,
                                             p_fc1t, p_fc2t, p_rw1t, p_rw2t, p_wcatT);

    // --- node projections ---
    proj_relu<8><<<cdiv(NLINK, 32), T>>>(x_link, Wp_link, bp_link, p_hlink, NLINK);
    proj_relu<16><<<cdiv(NFLOW, 32), T>>>(x_flow, Wp_flow, bp_flow, p_hflow, NFLOW);
    proj_relu<8><<<cdiv(NPATH, 32), T>>>(x_path, Wp_path, bp_path, p_hp0, NPATH);

    // --- z_src GEMMs ---
    {
        dim3 g1(1024 / 256, cdiv(NLINK, 128));
        mm_f16<1, false><<<g1, T, MM_SMEM_BYTES>>>(p_hlink, nullptr, p_fc1t, p_zs1,
                                                   NLINK, 1024, 256, nullptr, nullptr);
        dim3 g2(1024 / 256, cdiv(NFLOW, 128));
        mm_f16<1, false><<<g2, T, MM_SMEM_BYTES>>>(p_hflow, nullptr, p_fc2t, p_zs2,
                                                   NFLOW, 1024, 256, nullptr, nullptr);
    }

    // --- attn scores ---
    attn_score3<<<cdiv((NLINK + NFLOW + NPATH) * 32, T), T>>>(
        p_hlink, p_hflow, p_hp0, p_wl1, p_wl2, p_wr1, p_el1, p_el2, p_er1);

    // ================= conv 1 =================
    fill_conv_state<<<cdiv(NPATH * HIDN, T), T>>>(p_denom, p_agg);
    edge_softmax<true><<<cdiv(E1N, T), T>>>(p_el1, p_er1, e2p, p_ce, src1, dst1,
                                            p_ea, p_denom, E1N);
    edge_scatter<<<cdiv(E1N, 8), 512>>>(p_zs1, p_ea, p_denom, src1, dst1, p_agg, E1N);
    {
        dim3 g(1, cdiv(NPATH, 128));
        mm_f16<2, false><<<g, T, MM_SMEM_BYTES>>>(p_hp0, nullptr, p_rw1t, p_hp1,
                                                  NPATH, HIDN, 256, p_agg, nullptr);
    }

    // ================= conv 2 =================
    attn_score1<<<cdiv(NPATH * 32, T), T>>>(p_hp1, p_wr2, p_er2, NPATH);
    fill_conv_state<<<cdiv(NPATH * HIDN, T), T>>>(p_denom, p_agg);
    edge_softmax<false><<<cdiv(E2N, T), T>>>(p_el2, p_er2, nullptr, nullptr, src2, dst2,
                                             p_ea, p_denom, E2N);
    edge_scatter<<<cdiv(E2N, 8), 512>>>(p_zs2, p_ea, p_denom, src2, dst2, p_agg, E2N);
    {
        dim3 g(1, cdiv(NPATH, 128));
        mm_f16<2, false><<<g, T, MM_SMEM_BYTES>>>(p_hp1, nullptr, p_rw2t, p_hp2,
                                                  NPATH, HIDN, 256, p_agg, nullptr);
    }

    // ================= decoder =================
    {
        dim3 g(1, cdiv(NPATH, 128));
        mm_f16<3, true><<<g, T, MM_SMEM_BYTES>>>(p_hp2, p_hp1, p_wcatT, p_hidden,
                                                 NPATH, HIDN, 512, nullptr, b1);
    }
    decoder_out<<<cdiv(NPATH * 32, T), T>>>(p_hidden, W2, b2, out);
}

// round 15
// speedup vs baseline: 1.0368x; 1.0368x over previous
#include <cuda_runtime.h>
#include <cuda_fp16.h>
#include <cmath>
#include <cstdint>

#define NLINK 2000
#define NFLOW 30000
#define NPATH 50000
#define E1N   120000
#define E2N   120000
#define HIDN  256
#define NH    4
#define HD    256

// ---------------- scratch ----------------
__device__ __half g_h_link[NLINK * HIDN];
__device__ __half g_h_flow[NFLOW * HIDN];
__device__ __half g_h_path0[NPATH * HIDN];
__device__ __half g_h_path1[NPATH * HIDN];
__device__ __half g_h_path2[NPATH * HIDN];
__device__ __half g_zs1[NLINK * NH * HD];
__device__ __half g_zs2[NFLOW * NH * HD];
__device__ __half g_hidden[NPATH * HIDN];
__device__ float  g_el1[NLINK * NH];
__device__ float  g_er1[NPATH * NH];
__device__ float  g_el2[NFLOW * NH];
__device__ float  g_er2[NPATH * NH];
__device__ float  g_ea[E1N * NH];
__device__ float  g_denom[NPATH * NH];
__device__ float  g_agg[NPATH * HIDN];
__device__ float  g_wl1[HIDN * NH];
__device__ float  g_wr1[HIDN * NH];
__device__ float  g_wl2[HIDN * NH];
__device__ float  g_wr2[HIDN * NH];
__device__ float  g_ce[NH];
// fp16 transposed weights [N][K]
__device__ __half g_fc1t[NH * HD * HIDN];
__device__ __half g_fc2t[NH * HD * HIDN];
__device__ __half g_rw1t[HIDN * HIDN];
__device__ __half g_rw2t[HIDN * HIDN];
__device__ __half g_wcatT[HIDN * 2 * HIDN];

// ---------------- helpers ----------------
__device__ __forceinline__ void mma_f16(float* c, const uint32_t* a, const uint32_t* b) {
    asm volatile(
        "mma.sync.aligned.m16n8k16.row.col.f32.f16.f16.f32 "
        "{%0,%1,%2,%3}, {%4,%5,%6,%7}, {%8,%9}, {%0,%1,%2,%3};"
        : "+f"(c[0]), "+f"(c[1]), "+f"(c[2]), "+f"(c[3])
        : "r"(a[0]), "r"(a[1]), "r"(a[2]), "r"(a[3]), "r"(b[0]), "r"(b[1]));
}

__device__ __forceinline__ void ldsm_x4(uint32_t& r0, uint32_t& r1, uint32_t& r2,
                                        uint32_t& r3, uint32_t saddr) {
    asm volatile("ldmatrix.sync.aligned.m8n8.x4.shared.b16 {%0,%1,%2,%3}, [%4];"
                 : "=r"(r0), "=r"(r1), "=r"(r2), "=r"(r3) : "r"(saddr));
}

__device__ __forceinline__ void cp16(uint32_t saddr, const void* gaddr, int szbytes) {
    asm volatile("cp.async.cg.shared.global [%0], [%1], 16, %2;\n"
                 :: "r"(saddr), "l"(gaddr), "r"(szbytes));
}
__device__ __forceinline__ void cp_commit() { asm volatile("cp.async.commit_group;\n"); }
template <int W>
__device__ __forceinline__ void cp_wait() { asm volatile("cp.async.wait_group %0;\n" :: "n"(W)); }

__global__ void fill_conv_state(float* __restrict__ denom, float* __restrict__ agg) {
    int i = blockIdx.x * blockDim.x + threadIdx.x;
    if (i < NPATH * NH) denom[i] = 0.0f;
    if (i < NPATH * HIDN) agg[i] = 0.0f;
}

// transpose + fp16-convert all GEMM weights; fold W1 concat
__global__ void prep_weights(const float* __restrict__ fc1, const float* __restrict__ fc2,
                             const float* __restrict__ rw1, const float* __restrict__ rw2,
                             const float* __restrict__ W1,
                             __half* __restrict__ fc1t, __half* __restrict__ fc2t,
                             __half* __restrict__ rw1t, __half* __restrict__ rw2t,
                             __half* __restrict__ wcatT) {
    int i = blockIdx.x * blockDim.x + threadIdx.x;
    const int NFC = 1024 * 256, NRW = 256 * 256;
    if (i < NFC) {
        int n = i >> 8, k = i & 255;
        fc1t[i] = __float2half_rn(fc1[k * 1024 + n]);
        fc2t[i] = __float2half_rn(fc2[k * 1024 + n]);
    }
    if (i < NRW) {
        int n = i >> 8, k = i & 255;
        rw1t[i] = __float2half_rn(rw1[k * 256 + n]);
        rw2t[i] = __float2half_rn(rw2[k * 256 + n]);
    }
    if (i < 256 * 512) {
        int n = i >> 9, k = i & 511;
        float v = W1[k * 256 + n];
        if (k < 256) v += W1[(k + 512) * 256 + n];
        wcatT[i] = __float2half_rn(v);
    }
}

// ---------------- proj_relu ----------------
template <int KIN>
__global__ __launch_bounds__(256)
void proj_relu(const float* __restrict__ x, const float* __restrict__ W,
               const float* __restrict__ b, __half* __restrict__ out, int M) {
    __shared__ float xs[32][KIN];
    const int c = threadIdx.x;
    const int row0 = blockIdx.x * 32;
    for (int i = c; i < 32 * KIN; i += 256) {
        int r = i / KIN, k = i % KIN;
        xs[r][k] = (row0 + r < M) ? x[(size_t)(row0 + r) * KIN + k] : 0.0f;
    }
    float w[KIN];
#pragma unroll
    for (int k = 0; k < KIN; ++k) w[k] = W[k * HIDN + c];
    const float bias = b[c];
    __syncthreads();
    int rmax = min(32, M - row0);
    for (int r = 0; r < rmax; ++r) {
        float s = bias;
#pragma unroll
        for (int k = 0; k < KIN; ++k) s += xs[r][k] * w[k];
        out[(size_t)(row0 + r) * HIDN + c] = __float2half_rn(fmaxf(s, 0.0f));
    }
}

// one warp per output; 0..4095: wl1/wr1/wl2/wr2; 4096..4099: ce
__global__ void attn_reduce_all(
    const float* __restrict__ fcA, const float* __restrict__ aA, float* __restrict__ oA,
    const float* __restrict__ fcB, const float* __restrict__ aB, float* __restrict__ oB,
    const float* __restrict__ fcC, const float* __restrict__ aC, float* __restrict__ oC,
    const float* __restrict__ fcD, const float* __restrict__ aD, float* __restrict__ oD,
    const float* __restrict__ fcE, const float* __restrict__ aE, float* __restrict__ oE) {
    int gw = (blockIdx.x * blockDim.x + threadIdx.x) >> 5;
    int lane = threadIdx.x & 31;
    if (gw >= 4100) return;
    const float *fc, *at; float* out; int foff, aoff, oidx;
    if (gw < 4096) {
        int sel = gw >> 10, t = gw & 1023;
        int k = t >> 2, h = t & 3;
        switch (sel) {
            case 0: fc = fcA; at = aA; out = oA; break;
            case 1: fc = fcB; at = aB; out = oB; break;
            case 2: fc = fcC; at = aC; out = oC; break;
            default: fc = fcD; at = aD; out = oD; break;
        }
        foff = k * (NH * HD) + h * HD; aoff = h * HD; oidx = t;
    } else {
        int h = gw - 4096;
        fc = fcE; at = aE; out = oE;
        foff = h * HD; aoff = h * HD; oidx = h;
    }
    float s = 0.0f;
    for (int d = lane; d < HD; d += 32) s += fc[foff + d] * at[aoff + d];
#pragma unroll
    for (int o = 16; o > 0; o >>= 1) s += __shfl_down_sync(0xffffffffu, s, o);
    if (lane == 0) out[oidx] = s;
}

// ---------------- attn scores ----------------
__device__ __forceinline__ void attn_dot_store(const __half* __restrict__ row,
                                               const float* __restrict__ w,
                                               float* __restrict__ out, int lane) {
    float s0 = 0.f, s1 = 0.f, s2 = 0.f, s3 = 0.f;
    const __half2* r2 = (const __half2*)row;
#pragma unroll
    for (int j = 0; j < 4; ++j) {
        int i2 = lane + 32 * j;
        float2 f = __half22float2(r2[i2]);
        int k = 2 * i2;
        float4 w0 = *(const float4*)(w + 4 * k);
        float4 w1 = *(const float4*)(w + 4 * k + 4);
        s0 += f.x * w0.x + f.y * w1.x;
        s1 += f.x * w0.y + f.y * w1.y;
        s2 += f.x * w0.z + f.y * w1.z;
        s3 += f.x * w0.w + f.y * w1.w;
    }
#pragma unroll
    for (int o = 16; o > 0; o >>= 1) {
        s0 += __shfl_down_sync(0xffffffffu, s0, o);
        s1 += __shfl_down_sync(0xffffffffu, s1, o);
        s2 += __shfl_down_sync(0xffffffffu, s2, o);
        s3 += __shfl_down_sync(0xffffffffu, s3, o);
    }
    if (lane == 0) *(float4*)out = make_float4(s0, s1, s2, s3);
}

__global__ void attn_score3(const __half* __restrict__ hlink, const __half* __restrict__ hflow,
                            const __half* __restrict__ hpath,
                            const float* __restrict__ wl1, const float* __restrict__ wl2,
                            const float* __restrict__ wr1,
                            float* __restrict__ el1, float* __restrict__ el2,
                            float* __restrict__ er1) {
    int gw = (blockIdx.x * blockDim.x + threadIdx.x) >> 5;
    int lane = threadIdx.x & 31;
    if (gw >= NLINK + NFLOW + NPATH) return;
    const __half* row; const float* w; float* out;
    if (gw < NLINK)               { row = hlink + (size_t)gw * HIDN; w = wl1; out = el1 + gw * 4; }
    else if (gw < NLINK + NFLOW)  { int r = gw - NLINK; row = hflow + (size_t)r * HIDN; w = wl2; out = el2 + r * 4; }
    else                          { int r = gw - NLINK - NFLOW; row = hpath + (size_t)r * HIDN; w = wr1; out = er1 + r * 4; }
    attn_dot_store(row, w, out, lane);
}

__global__ void attn_score1(const __half* __restrict__ hfeat, const float* __restrict__ w,
                            float* __restrict__ out, int M) {
    int gw = (blockIdx.x * blockDim.x + threadIdx.x) >> 5;
    int lane = threadIdx.x & 31;
    if (gw >= M) return;
    attn_dot_store(hfeat + (size_t)gw * HIDN, w, out + gw * 4, lane);
}

// ---------------- fused edge softmax ----------------
template <bool HAS_EE>
__global__ void edge_softmax(const float* __restrict__ el, const float* __restrict__ er,
                             const float* __restrict__ ef, const float* __restrict__ ce,
                             const int* __restrict__ src, const int* __restrict__ dst,
                             float* __restrict__ a_out, float* __restrict__ denom, int E) {
    int e = blockIdx.x * blockDim.x + threadIdx.x;
    if (e >= E) return;
    int s = src[e], d = dst[e];
    float4 a = *(const float4*)(el + s * 4);
    float4 b = *(const float4*)(er + d * 4);
    float v[4] = { a.x + b.x, a.y + b.y, a.z + b.z, a.w + b.w };
    if (HAS_EE) {
        float f = ef[e];
        float4 c = *(const float4*)ce;
        v[0] += f * c.x; v[1] += f * c.y; v[2] += f * c.z; v[3] += f * c.w;
    }
#pragma unroll
    for (int h = 0; h < 4; ++h) {
        float lv = v[h] > 0.0f ? v[h] : 0.2f * v[h];
        v[h] = __expf(lv);
    }
    *(float4*)(a_out + e * 4) = make_float4(v[0], v[1], v[2], v[3]);
    atomicAdd(&denom[d * 4 + 0], v[0]);
    atomicAdd(&denom[d * 4 + 1], v[1]);
    atomicAdd(&denom[d * 4 + 2], v[2]);
    atomicAdd(&denom[d * 4 + 3], v[3]);
}

// ---------------- edge scatter: 8 edges per 512-thread block ----------------
__global__ __launch_bounds__(512)
void edge_scatter(const __half* __restrict__ zs, const float* __restrict__ a_in,
                  const float* __restrict__ denom,
                  const int* __restrict__ src, const int* __restrict__ dst,
                  float* __restrict__ agg, int E) {
    int e = blockIdx.x * 8 + (threadIdx.x >> 6);
    if (e >= E) return;
    int t = threadIdx.x & 63;
    int s = src[e], d = dst[e];
    float al[NH];
    float4 av = *(const float4*)(a_in + e * 4);
    float4 dv = *(const float4*)(denom + d * 4);
    al[0] = 0.25f * av.x / fmaxf(dv.x, 1e-9f);
    al[1] = 0.25f * av.y / fmaxf(dv.y, 1e-9f);
    al[2] = 0.25f * av.z / fmaxf(dv.z, 1e-9f);
    al[3] = 0.25f * av.w / fmaxf(dv.w, 1e-9f);
    const uint2* z = (const uint2*)(zs + (size_t)s * (NH * HD));
    float4 r = make_float4(0.f, 0.f, 0.f, 0.f);
#pragma unroll
    for (int h = 0; h < NH; ++h) {
        uint2 u = __ldg(&z[h * 64 + t]);
        float2 f0 = __half22float2(*(const __half2*)&u.x);
        float2 f1 = __half22float2(*(const __half2*)&u.y);
        r.x += al[h] * f0.x; r.y += al[h] * f0.y;
        r.z += al[h] * f1.x; r.w += al[h] * f1.y;
    }
    float* outp = agg + (size_t)d * HIDN + t * 4;
    asm volatile("red.global.add.v4.f32 [%0], {%1,%2,%3,%4};"
                 :: "l"(outp), "f"(r.x), "f"(r.y), "f"(r.z), "f"(r.w) : "memory");
}

__global__ void decoder_out(const __half* __restrict__ hidden, const float* __restrict__ W2,
                            const float* __restrict__ b2, float* __restrict__ out) {
    int gw = (blockIdx.x * blockDim.x + threadIdx.x) >> 5;
    int lane = threadIdx.x & 31;
    if (gw >= NPATH) return;
    const __half2* hrow = (const __half2*)(hidden + (size_t)gw * HIDN);
    float s0 = 0.f, s1 = 0.f;
#pragma unroll
    for (int j = 0; j < 4; ++j) {
        int i2 = lane + 32 * j;
        float2 f = __half22float2(hrow[i2]);
        int k = 2 * i2;
        float2 w0 = *(const float2*)(W2 + 2 * k);
        float2 w1 = *(const float2*)(W2 + 2 * k + 2);
        s0 += f.x * w0.x + f.y * w1.x;
        s1 += f.x * w0.y + f.y * w1.y;
    }
#pragma unroll
    for (int o = 16; o > 0; o >>= 1) {
        s0 += __shfl_down_sync(0xffffffffu, s0, o);
        s1 += __shfl_down_sync(0xffffffffu, s1, o);
    }
    if (lane == 0) *(float2*)(out + gw * 2) = make_float2(s0 + b2[0], s1 + b2[1]);
}

// ---------------- fp16 tensor-core GEMM (R9 config: 128x128, 2 CTA/SM) ----------------
// C[M,N] = epi(A[M,K] @ Bt[N,K]^T). Block 128x128, 8 warps of 64x32, BK=32.
// 3-stage cp.async; smem rows padded to 40 halves (80B) -> LDSM conflict-free.
// EPI: 1 = fp16 out, 2 = relu(+add[M,N]) fp16, 3 = relu(+bias[N]) fp16.
#define MM_STAGES 3
#define MM_TILE_U32 (128 * 20)
#define MM_SMEM_BYTES (MM_STAGES * 2 * MM_TILE_U32 * 4)
template <int EPI, bool SPLITA>
__global__ __launch_bounds__(256, 2)
void mm_f16(const __half* __restrict__ A, const __half* __restrict__ A2,
            const __half* __restrict__ Bt, void* __restrict__ Cout,
            int M, int N, int K,
            const float* __restrict__ add, const float* __restrict__ bias) {
    extern __shared__ uint32_t smem[];
    uint32_t* AsB = smem;
    uint32_t* BsB = smem + MM_STAGES * MM_TILE_U32;
    const int tid = threadIdx.x;
    const int lane = tid & 31, wid = tid >> 5;
    const int g = lane >> 2, tig = lane & 3;
    const int warp_m = (wid >> 2) * 64, warp_n = (wid & 3) * 32;
    const int row0 = blockIdx.y * 128, col0 = blockIdx.x * 128;

    float acc[4][4][4];
#pragma unroll
    for (int i = 0; i < 4; ++i)
#pragma unroll
        for (int j = 0; j < 4; ++j)
#pragma unroll
            for (int r = 0; r < 4; ++r) acc[i][j][r] = 0.0f;

    auto issue = [&](int st, int k0) {
#pragma unroll
        for (int p = 0; p < 2; ++p) {
            int q = tid + 256 * p;
            int row = q >> 2, cik = q & 3;
            int c = k0 + cik * 8;
            int r = row0 + row;
            const __half* asrc = A;
            int sz = 0;
            if (r < M) {
                sz = 16;
                if (SPLITA) asrc = (c < HIDN) ? (A + (size_t)r * HIDN + c)
                                              : (A2 + (size_t)r * HIDN + (c - HIDN));
                else        asrc = A + (size_t)r * K + c;
            }
            cp16((uint32_t)__cvta_generic_to_shared(AsB + st * MM_TILE_U32 + row * 20 + cik * 4),
                 asrc, sz);
            const __half* bsrc = Bt + (size_t)(col0 + row) * K + c;
            cp16((uint32_t)__cvta_generic_to_shared(BsB + st * MM_TILE_U32 + row * 20 + cik * 4),
                 bsrc, 16);
        }
        cp_commit();
    };

    const uint32_t a_lane_off = ((lane & 7) + 8 * ((lane >> 3) & 1)) * 80 + 16 * (lane >> 4);
    const uint32_t b_lane_off = ((lane & 7) + 8 * (lane >> 4)) * 80 + 16 * ((lane >> 3) & 1);

    const int nIter = K / 32;
    issue(0, 0);
    issue(1, 32);
    for (int it = 0; it < nIter; ++it) {
        if (it == nIter - 1) cp_wait<0>(); else cp_wait<1>();
        __syncthreads();
        if (it + 2 < nIter) issue((it + 2) % MM_STAGES, (it + 2) * 32);
        const uint32_t As_byte =
            (uint32_t)__cvta_generic_to_shared(AsB + (it % MM_STAGES) * MM_TILE_U32);
        const uint32_t Bs_byte =
            (uint32_t)__cvta_generic_to_shared(BsB + (it % MM_STAGES) * MM_TILE_U32);
#pragma unroll
        for (int ks = 0; ks < 2; ++ks) {
            uint32_t af[4][4], bf[4][2];
#pragma unroll
            for (int mi = 0; mi < 4; ++mi)
                ldsm_x4(af[mi][0], af[mi][1], af[mi][2], af[mi][3],
                        As_byte + (warp_m + 16 * mi) * 80 + ks * 32 + a_lane_off);
#pragma unroll
            for (int np = 0; np < 2; ++np)
                ldsm_x4(bf[2 * np][0], bf[2 * np][1], bf[2 * np + 1][0], bf[2 * np + 1][1],
                        Bs_byte + (warp_n + 16 * np) * 80 + ks * 32 + b_lane_off);
#pragma unroll
            for (int mi = 0; mi < 4; ++mi)
#pragma unroll
                for (int ni = 0; ni < 4; ++ni)
                    mma_f16(acc[mi][ni], af[mi], bf[ni]);
        }
    }

#pragma unroll
    for (int mi = 0; mi < 4; ++mi) {
#pragma unroll
        for (int ni = 0; ni < 4; ++ni) {
            int rA = row0 + warp_m + 16 * mi + g;
            int cA = col0 + warp_n + 8 * ni + 2 * tig;
#pragma unroll
            for (int half_ = 0; half_ < 2; ++half_) {
                int r = rA + half_ * 8;
                if (r >= M) continue;
                float v0 = acc[mi][ni][half_ * 2 + 0];
                float v1 = acc[mi][ni][half_ * 2 + 1];
                if (EPI == 2) {
                    v0 = fmaxf(v0 + add[(size_t)r * N + cA + 0], 0.0f);
                    v1 = fmaxf(v1 + add[(size_t)r * N + cA + 1], 0.0f);
                } else if (EPI == 3) {
                    v0 = fmaxf(v0 + bias[cA + 0], 0.0f);
                    v1 = fmaxf(v1 + bias[cA + 1], 0.0f);
                }
                __half2* C = (__half2*)Cout;
                C[((size_t)r * N + cA) >> 1] = __floats2half2_rn(v0, v1);
            }
        }
    }
}

// ---------------- host launch ----------------
static inline int cdiv(int a, int b) { return (a + b - 1) / b; }

extern "C" void kernel_launch(void* const* d_in, const int* in_sizes, int n_in,
                              void* d_out, int out_size) {
    (void)in_sizes; (void)n_in; (void)out_size;
    const float* x_link  = (const float*)d_in[0];
    const float* x_flow  = (const float*)d_in[1];
    const float* x_path  = (const float*)d_in[2];
    const float* e2p     = (const float*)d_in[3];
    const float* Wp_link = (const float*)d_in[4];
    const float* bp_link = (const float*)d_in[5];
    const float* Wp_flow = (const float*)d_in[6];
    const float* bp_flow = (const float*)d_in[7];
    const float* Wp_path = (const float*)d_in[8];
    const float* bp_path = (const float*)d_in[9];
    const float* fc_src1 = (const float*)d_in[10];
    const float* fc_dst1 = (const float*)d_in[11];
    const float* fc_e1   = (const float*)d_in[12];
    const float* attn_l1 = (const float*)d_in[13];
    const float* attn_r1 = (const float*)d_in[14];
    const float* attn_e1 = (const float*)d_in[15];
    const float* res_W1  = (const float*)d_in[16];
    const float* fc_src2 = (const float*)d_in[17];
    const float* fc_dst2 = (const float*)d_in[18];
    const float* attn_l2 = (const float*)d_in[19];
    const float* attn_r2 = (const float*)d_in[20];
    const float* res_W2  = (const float*)d_in[21];
    const float* W1      = (const float*)d_in[22];
    const float* b1      = (const float*)d_in[23];
    const float* W2      = (const float*)d_in[24];
    const float* b2      = (const float*)d_in[25];
    const int*   src1    = (const int*)d_in[26];
    const int*   dst1    = (const int*)d_in[27];
    const int*   src2    = (const int*)d_in[28];
    const int*   dst2    = (const int*)d_in[29];
    float* out = (float*)d_out;

#define SYMF(p, s) float* p; cudaGetSymbolAddress((void**)&p, s)
#define SYMH(p, s) __half* p; cudaGetSymbolAddress((void**)&p, s)
    SYMH(p_hlink, g_h_link);  SYMH(p_hflow, g_h_flow);
    SYMH(p_hp0, g_h_path0);   SYMH(p_hp1, g_h_path1);   SYMH(p_hp2, g_h_path2);
    SYMH(p_zs1, g_zs1);       SYMH(p_zs2, g_zs2);       SYMH(p_hidden, g_hidden);
    SYMF(p_el1, g_el1);       SYMF(p_er1, g_er1);
    SYMF(p_el2, g_el2);       SYMF(p_er2, g_er2);
    SYMF(p_ea, g_ea);         SYMF(p_denom, g_denom);   SYMF(p_agg, g_agg);
    SYMF(p_wl1, g_wl1);       SYMF(p_wr1, g_wr1);
    SYMF(p_wl2, g_wl2);       SYMF(p_wr2, g_wr2);       SYMF(p_ce, g_ce);
    SYMH(p_fc1t, g_fc1t);     SYMH(p_fc2t, g_fc2t);
    SYMH(p_rw1t, g_rw1t);     SYMH(p_rw2t, g_rw2t);     SYMH(p_wcatT, g_wcatT);
#undef SYMF
#undef SYMH

    const int T = 256;

    // one-time host-object setup (no device memory involved; identical work every call)
    static cudaStream_t s2 = nullptr;
    static cudaEvent_t evFork = nullptr, evJoin = nullptr;
    if (s2 == nullptr) {
        cudaStreamCreateWithFlags(&s2, cudaStreamNonBlocking);
        cudaEventCreateWithFlags(&evFork, cudaEventDisableTiming);
        cudaEventCreateWithFlags(&evJoin, cudaEventDisableTiming);
        cudaFuncSetAttribute(mm_f16<1, false>, cudaFuncAttributeMaxDynamicSharedMemorySize, MM_SMEM_BYTES);
        cudaFuncSetAttribute(mm_f16<2, false>, cudaFuncAttributeMaxDynamicSharedMemorySize, MM_SMEM_BYTES);
        cudaFuncSetAttribute(mm_f16<3, true>,  cudaFuncAttributeMaxDynamicSharedMemorySize, MM_SMEM_BYTES);
    }

    // --- weight prep ---
    attn_reduce_all<<<cdiv(4100 * 32, T), T>>>(
        fc_src1, attn_l1, p_wl1,  fc_dst1, attn_r1, p_wr1,
        fc_src2, attn_l2, p_wl2,  fc_dst2, attn_r2, p_wr2,
        fc_e1, attn_e1, p_ce);
    prep_weights<<<cdiv(1024 * 256, T), T>>>(fc_src1, fc_src2, res_W1, res_W2, W1,
                                             p_fc1t, p_fc2t, p_rw1t, p_rw2t, p_wcatT);

    // --- node projections ---
    proj_relu<8><<<cdiv(NLINK, 32), T>>>(x_link, Wp_link, bp_link, p_hlink, NLINK);
    proj_relu<16><<<cdiv(NFLOW, 32), T>>>(x_flow, Wp_flow, bp_flow, p_hflow, NFLOW);
    proj_relu<8><<<cdiv(NPATH, 32), T>>>(x_path, Wp_path, bp_path, p_hp0, NPATH);

    // ---- fork: zs2 GEMM (only needed by conv2's scatter) runs on side stream ----
    cudaEventRecord(evFork, 0);
    cudaStreamWaitEvent(s2, evFork, 0);
    {
        dim3 g2(1024 / 128, cdiv(NFLOW, 128));
        mm_f16<1, false><<<g2, T, MM_SMEM_BYTES, s2>>>(p_hflow, nullptr, p_fc2t, p_zs2,
                                                       NFLOW, 1024, 256, nullptr, nullptr);
    }
    cudaEventRecord(evJoin, s2);

    // --- zs1 GEMM (small; needed by conv1) on main stream ---
    {
        dim3 g1(1024 / 128, cdiv(NLINK, 128));
        mm_f16<1, false><<<g1, T, MM_SMEM_BYTES>>>(p_hlink, nullptr, p_fc1t, p_zs1,
                                                   NLINK, 1024, 256, nullptr, nullptr);
    }

    // --- attn scores ---
    attn_score3<<<cdiv((NLINK + NFLOW + NPATH) * 32, T), T>>>(
        p_hlink, p_hflow, p_hp0, p_wl1, p_wl2, p_wr1, p_el1, p_el2, p_er1);

    // ================= conv 1 (overlaps with zs2 GEMM) =================
    fill_conv_state<<<cdiv(NPATH * HIDN, T), T>>>(p_denom, p_agg);
    edge_softmax<true><<<cdiv(E1N, T), T>>>(p_el1, p_er1, e2p, p_ce, src1, dst1,
                                            p_ea, p_denom, E1N);
    edge_scatter<<<cdiv(E1N, 8), 512>>>(p_zs1, p_ea, p_denom, src1, dst1, p_agg, E1N);
    {
        dim3 g(HIDN / 128, cdiv(NPATH, 128));
        mm_f16<2, false><<<g, T, MM_SMEM_BYTES>>>(p_hp0, nullptr, p_rw1t, p_hp1,
                                                  NPATH, HIDN, 256, p_agg, nullptr);
    }

    // ================= conv 2 =================
    attn_score1<<<cdiv(NPATH * 32, T), T>>>(p_hp1, p_wr2, p_er2, NPATH);
    fill_conv_state<<<cdiv(NPATH * HIDN, T), T>>>(p_denom, p_agg);
    edge_softmax<false><<<cdiv(E2N, T), T>>>(p_el2, p_er2, nullptr, nullptr, src2, dst2,
                                             p_ea, p_denom, E2N);
    // join: scatter2 needs zs2
    cudaStreamWaitEvent(0, evJoin, 0);
    edge_scatter<<<cdiv(E2N, 8), 512>>>(p_zs2, p_ea, p_denom, src2, dst2, p_agg, E2N);
    {
        dim3 g(HIDN / 128, cdiv(NPATH, 128));
        mm_f16<2, false><<<g, T, MM_SMEM_BYTES>>>(p_hp1, nullptr, p_rw2t, p_hp2,
                                                  NPATH, HIDN, 256, p_agg, nullptr);
    }

    // ================= decoder =================
    {
        dim3 g(HIDN / 128, cdiv(NPATH, 128));
        mm_f16<3, true><<<g, T, MM_SMEM_BYTES>>>(p_hp2, p_hp1, p_wcatT, p_hidden,
                                                 NPATH, HIDN, 512, nullptr, b1);
    }
    decoder_out<<<cdiv(NPATH * 32, T), T>>>(p_hidden, W2, b2, out);
}

// round 17
// speedup vs baseline: 1.0608x; 1.0232x over previous
#include <cuda_runtime.h>
#include <cuda_fp16.h>
#include <cmath>
#include <cstdint>

#define NLINK 2000
#define NFLOW 30000
#define NPATH 50000
#define E1N   120000
#define E2N   120000
#define HIDN  256
#define NH    4
#define HD    256

// ---------------- scratch ----------------
__device__ __half g_h_link[NLINK * HIDN];
__device__ __half g_h_flow[NFLOW * HIDN];
__device__ __half g_h_path0[NPATH * HIDN];
__device__ __half g_h_path1[NPATH * HIDN];
__device__ __half g_h_path2[NPATH * HIDN];
__device__ __half g_zs1[NLINK * NH * HD];
__device__ __half g_zs2[NFLOW * NH * HD];
__device__ __half g_hidden[NPATH * HIDN];
__device__ float  g_el1[NLINK * NH];
__device__ float  g_er1[NPATH * NH];
__device__ float  g_el2[NFLOW * NH];
__device__ float  g_er2[NPATH * NH];
__device__ float  g_ea1[E1N * NH];
__device__ float  g_ea2[E2N * NH];
__device__ float  g_denom1[NPATH * NH];
__device__ float  g_denom2[NPATH * NH];
__device__ float  g_agg1[NPATH * HIDN];
__device__ float  g_agg2[NPATH * HIDN];
__device__ float  g_wl1[HIDN * NH];
__device__ float  g_wr1[HIDN * NH];
__device__ float  g_wl2[HIDN * NH];
__device__ float  g_wr2[HIDN * NH];
__device__ float  g_ce[NH];
// fp16 transposed weights [N][K]
__device__ __half g_fc1t[NH * HD * HIDN];
__device__ __half g_fc2t[NH * HD * HIDN];
__device__ __half g_rw1t[HIDN * HIDN];
__device__ __half g_rw2t[HIDN * HIDN];
__device__ __half g_wcatT[HIDN * 2 * HIDN];

// ---------------- helpers ----------------
__device__ __forceinline__ void mma_f16(float* c, const uint32_t* a, const uint32_t* b) {
    asm volatile(
        "mma.sync.aligned.m16n8k16.row.col.f32.f16.f16.f32 "
        "{%0,%1,%2,%3}, {%4,%5,%6,%7}, {%8,%9}, {%0,%1,%2,%3};"
        : "+f"(c[0]), "+f"(c[1]), "+f"(c[2]), "+f"(c[3])
        : "r"(a[0]), "r"(a[1]), "r"(a[2]), "r"(a[3]), "r"(b[0]), "r"(b[1]));
}

__device__ __forceinline__ void ldsm_x4(uint32_t& r0, uint32_t& r1, uint32_t& r2,
                                        uint32_t& r3, uint32_t saddr) {
    asm volatile("ldmatrix.sync.aligned.m8n8.x4.shared.b16 {%0,%1,%2,%3}, [%4];"
                 : "=r"(r0), "=r"(r1), "=r"(r2), "=r"(r3) : "r"(saddr));
}

__device__ __forceinline__ void cp16(uint32_t saddr, const void* gaddr, int szbytes) {
    asm volatile("cp.async.cg.shared.global [%0], [%1], 16, %2;\n"
                 :: "r"(saddr), "l"(gaddr), "r"(szbytes));
}
__device__ __forceinline__ void cp_commit() { asm volatile("cp.async.commit_group;\n"); }
template <int W>
__device__ __forceinline__ void cp_wait() { asm volatile("cp.async.wait_group %0;\n" :: "n"(W)); }

__global__ void fill_conv_state(float* __restrict__ denom, float* __restrict__ agg) {
    int i = blockIdx.x * blockDim.x + threadIdx.x;
    if (i < NPATH * NH) denom[i] = 0.0f;
    if (i < NPATH * HIDN) agg[i] = 0.0f;
}

// transpose + fp16-convert all GEMM weights; fold W1 concat
__global__ void prep_weights(const float* __restrict__ fc1, const float* __restrict__ fc2,
                             const float* __restrict__ rw1, const float* __restrict__ rw2,
                             const float* __restrict__ W1,
                             __half* __restrict__ fc1t, __half* __restrict__ fc2t,
                             __half* __restrict__ rw1t, __half* __restrict__ rw2t,
                             __half* __restrict__ wcatT) {
    int i = blockIdx.x * blockDim.x + threadIdx.x;
    const int NFC = 1024 * 256, NRW = 256 * 256;
    if (i < NFC) {
        int n = i >> 8, k = i & 255;
        fc1t[i] = __float2half_rn(fc1[k * 1024 + n]);
        fc2t[i] = __float2half_rn(fc2[k * 1024 + n]);
    }
    if (i < NRW) {
        int n = i >> 8, k = i & 255;
        rw1t[i] = __float2half_rn(rw1[k * 256 + n]);
        rw2t[i] = __float2half_rn(rw2[k * 256 + n]);
    }
    if (i < 256 * 512) {
        int n = i >> 9, k = i & 511;
        float v = W1[k * 256 + n];
        if (k < 256) v += W1[(k + 512) * 256 + n];
        wcatT[i] = __float2half_rn(v);
    }
}

// ---------------- proj_relu ----------------
template <int KIN>
__global__ __launch_bounds__(256)
void proj_relu(const float* __restrict__ x, const float* __restrict__ W,
               const float* __restrict__ b, __half* __restrict__ out, int M) {
    __shared__ float xs[32][KIN];
    const int c = threadIdx.x;
    const int row0 = blockIdx.x * 32;
    for (int i = c; i < 32 * KIN; i += 256) {
        int r = i / KIN, k = i % KIN;
        xs[r][k] = (row0 + r < M) ? x[(size_t)(row0 + r) * KIN + k] : 0.0f;
    }
    float w[KIN];
#pragma unroll
    for (int k = 0; k < KIN; ++k) w[k] = W[k * HIDN + c];
    const float bias = b[c];
    __syncthreads();
    int rmax = min(32, M - row0);
    for (int r = 0; r < rmax; ++r) {
        float s = bias;
#pragma unroll
        for (int k = 0; k < KIN; ++k) s += xs[r][k] * w[k];
        out[(size_t)(row0 + r) * HIDN + c] = __float2half_rn(fmaxf(s, 0.0f));
    }
}

// one warp per output; 0..4095: wl1/wr1/wl2/wr2; 4096..4099: ce
__global__ void attn_reduce_all(
    const float* __restrict__ fcA, const float* __restrict__ aA, float* __restrict__ oA,
    const float* __restrict__ fcB, const float* __restrict__ aB, float* __restrict__ oB,
    const float* __restrict__ fcC, const float* __restrict__ aC, float* __restrict__ oC,
    const float* __restrict__ fcD, const float* __restrict__ aD, float* __restrict__ oD,
    const float* __restrict__ fcE, const float* __restrict__ aE, float* __restrict__ oE) {
    int gw = (blockIdx.x * blockDim.x + threadIdx.x) >> 5;
    int lane = threadIdx.x & 31;
    if (gw >= 4100) return;
    const float *fc, *at; float* out; int foff, aoff, oidx;
    if (gw < 4096) {
        int sel = gw >> 10, t = gw & 1023;
        int k = t >> 2, h = t & 3;
        switch (sel) {
            case 0: fc = fcA; at = aA; out = oA; break;
            case 1: fc = fcB; at = aB; out = oB; break;
            case 2: fc = fcC; at = aC; out = oC; break;
            default: fc = fcD; at = aD; out = oD; break;
        }
        foff = k * (NH * HD) + h * HD; aoff = h * HD; oidx = t;
    } else {
        int h = gw - 4096;
        fc = fcE; at = aE; out = oE;
        foff = h * HD; aoff = h * HD; oidx = h;
    }
    float s = 0.0f;
    for (int d = lane; d < HD; d += 32) s += fc[foff + d] * at[aoff + d];
#pragma unroll
    for (int o = 16; o > 0; o >>= 1) s += __shfl_down_sync(0xffffffffu, s, o);
    if (lane == 0) out[oidx] = s;
}

// ---------------- attn scores ----------------
__device__ __forceinline__ void attn_dot_store(const __half* __restrict__ row,
                                               const float* __restrict__ w,
                                               float* __restrict__ out, int lane) {
    float s0 = 0.f, s1 = 0.f, s2 = 0.f, s3 = 0.f;
    const __half2* r2 = (const __half2*)row;
#pragma unroll
    for (int j = 0; j < 4; ++j) {
        int i2 = lane + 32 * j;
        float2 f = __half22float2(r2[i2]);
        int k = 2 * i2;
        float4 w0 = *(const float4*)(w + 4 * k);
        float4 w1 = *(const float4*)(w + 4 * k + 4);
        s0 += f.x * w0.x + f.y * w1.x;
        s1 += f.x * w0.y + f.y * w1.y;
        s2 += f.x * w0.z + f.y * w1.z;
        s3 += f.x * w0.w + f.y * w1.w;
    }
#pragma unroll
    for (int o = 16; o > 0; o >>= 1) {
        s0 += __shfl_down_sync(0xffffffffu, s0, o);
        s1 += __shfl_down_sync(0xffffffffu, s1, o);
        s2 += __shfl_down_sync(0xffffffffu, s2, o);
        s3 += __shfl_down_sync(0xffffffffu, s3, o);
    }
    if (lane == 0) *(float4*)out = make_float4(s0, s1, s2, s3);
}

__global__ void attn_score3(const __half* __restrict__ hlink, const __half* __restrict__ hflow,
                            const __half* __restrict__ hpath,
                            const float* __restrict__ wl1, const float* __restrict__ wl2,
                            const float* __restrict__ wr1,
                            float* __restrict__ el1, float* __restrict__ el2,
                            float* __restrict__ er1) {
    int gw = (blockIdx.x * blockDim.x + threadIdx.x) >> 5;
    int lane = threadIdx.x & 31;
    if (gw >= NLINK + NFLOW + NPATH) return;
    const __half* row; const float* w; float* out;
    if (gw < NLINK)               { row = hlink + (size_t)gw * HIDN; w = wl1; out = el1 + gw * 4; }
    else if (gw < NLINK + NFLOW)  { int r = gw - NLINK; row = hflow + (size_t)r * HIDN; w = wl2; out = el2 + r * 4; }
    else                          { int r = gw - NLINK - NFLOW; row = hpath + (size_t)r * HIDN; w = wr1; out = er1 + r * 4; }
    attn_dot_store(row, w, out, lane);
}

__global__ void attn_score1(const __half* __restrict__ hfeat, const float* __restrict__ w,
                            float* __restrict__ out, int M) {
    int gw = (blockIdx.x * blockDim.x + threadIdx.x) >> 5;
    int lane = threadIdx.x & 31;
    if (gw >= M) return;
    attn_dot_store(hfeat + (size_t)gw * HIDN, w, out + gw * 4, lane);
}

// ---------------- fused edge softmax ----------------
template <bool HAS_EE>
__global__ void edge_softmax(const float* __restrict__ el, const float* __restrict__ er,
                             const float* __restrict__ ef, const float* __restrict__ ce,
                             const int* __restrict__ src, const int* __restrict__ dst,
                             float* __restrict__ a_out, float* __restrict__ denom, int E) {
    int e = blockIdx.x * blockDim.x + threadIdx.x;
    if (e >= E) return;
    int s = src[e], d = dst[e];
    float4 a = *(const float4*)(el + s * 4);
    float4 b = *(const float4*)(er + d * 4);
    float v[4] = { a.x + b.x, a.y + b.y, a.z + b.z, a.w + b.w };
    if (HAS_EE) {
        float f = ef[e];
        float4 c = *(const float4*)ce;
        v[0] += f * c.x; v[1] += f * c.y; v[2] += f * c.z; v[3] += f * c.w;
    }
#pragma unroll
    for (int h = 0; h < 4; ++h) {
        float lv = v[h] > 0.0f ? v[h] : 0.2f * v[h];
        v[h] = __expf(lv);
    }
    *(float4*)(a_out + e * 4) = make_float4(v[0], v[1], v[2], v[3]);
    atomicAdd(&denom[d * 4 + 0], v[0]);
    atomicAdd(&denom[d * 4 + 1], v[1]);
    atomicAdd(&denom[d * 4 + 2], v[2]);
    atomicAdd(&denom[d * 4 + 3], v[3]);
}

// ---------------- edge scatter: 8 edges per 512-thread block ----------------
__global__ __launch_bounds__(512)
void edge_scatter(const __half* __restrict__ zs, const float* __restrict__ a_in,
                  const float* __restrict__ denom,
                  const int* __restrict__ src, const int* __restrict__ dst,
                  float* __restrict__ agg, int E) {
    int e = blockIdx.x * 8 + (threadIdx.x >> 6);
    if (e >= E) return;
    int t = threadIdx.x & 63;
    int s = src[e], d = dst[e];
    float al[NH];
    float4 av = *(const float4*)(a_in + e * 4);
    float4 dv = *(const float4*)(denom + d * 4);
    al[0] = 0.25f * av.x / fmaxf(dv.x, 1e-9f);
    al[1] = 0.25f * av.y / fmaxf(dv.y, 1e-9f);
    al[2] = 0.25f * av.z / fmaxf(dv.z, 1e-9f);
    al[3] = 0.25f * av.w / fmaxf(dv.w, 1e-9f);
    const uint2* z = (const uint2*)(zs + (size_t)s * (NH * HD));
    float4 r = make_float4(0.f, 0.f, 0.f, 0.f);
#pragma unroll
    for (int h = 0; h < NH; ++h) {
        uint2 u = __ldg(&z[h * 64 + t]);
        float2 f0 = __half22float2(*(const __half2*)&u.x);
        float2 f1 = __half22float2(*(const __half2*)&u.y);
        r.x += al[h] * f0.x; r.y += al[h] * f0.y;
        r.z += al[h] * f1.x; r.w += al[h] * f1.y;
    }
    float* outp = agg + (size_t)d * HIDN + t * 4;
    asm volatile("red.global.add.v4.f32 [%0], {%1,%2,%3,%4};"
                 :: "l"(outp), "f"(r.x), "f"(r.y), "f"(r.z), "f"(r.w) : "memory");
}

__global__ void decoder_out(const __half* __restrict__ hidden, const float* __restrict__ W2,
                            const float* __restrict__ b2, float* __restrict__ out) {
    int gw = (blockIdx.x * blockDim.x + threadIdx.x) >> 5;
    int lane = threadIdx.x & 31;
    if (gw >= NPATH) return;
    const __half2* hrow = (const __half2*)(hidden + (size_t)gw * HIDN);
    float s0 = 0.f, s1 = 0.f;
#pragma unroll
    for (int j = 0; j < 4; ++j) {
        int i2 = lane + 32 * j;
        float2 f = __half22float2(hrow[i2]);
        int k = 2 * i2;
        float2 w0 = *(const float2*)(W2 + 2 * k);
        float2 w1 = *(const float2*)(W2 + 2 * k + 2);
        s0 += f.x * w0.x + f.y * w1.x;
        s1 += f.x * w0.y + f.y * w1.y;
    }
#pragma unroll
    for (int o = 16; o > 0; o >>= 1) {
        s0 += __shfl_down_sync(0xffffffffu, s0, o);
        s1 += __shfl_down_sync(0xffffffffu, s1, o);
    }
    if (lane == 0) *(float2*)(out + gw * 2) = make_float2(s0 + b2[0], s1 + b2[1]);
}

// ---------------- fp16 tensor-core GEMM (128x128, 2 CTA/SM) ----------------
#define MM_STAGES 3
#define MM_TILE_U32 (128 * 20)
#define MM_SMEM_BYTES (MM_STAGES * 2 * MM_TILE_U32 * 4)
template <int EPI, bool SPLITA>
__global__ __launch_bounds__(256, 2)
void mm_f16(const __half* __restrict__ A, const __half* __restrict__ A2,
            const __half* __restrict__ Bt, void* __restrict__ Cout,
            int M, int N, int K,
            const float* __restrict__ add, const float* __restrict__ bias) {
    extern __shared__ uint32_t smem[];
    uint32_t* AsB = smem;
    uint32_t* BsB = smem + MM_STAGES * MM_TILE_U32;
    const int tid = threadIdx.x;
    const int lane = tid & 31, wid = tid >> 5;
    const int g = lane >> 2, tig = lane & 3;
    const int warp_m = (wid >> 2) * 64, warp_n = (wid & 3) * 32;
    const int row0 = blockIdx.y * 128, col0 = blockIdx.x * 128;

    float acc[4][4][4];
#pragma unroll
    for (int i = 0; i < 4; ++i)
#pragma unroll
        for (int j = 0; j < 4; ++j)
#pragma unroll
            for (int r = 0; r < 4; ++r) acc[i][j][r] = 0.0f;

    auto issue = [&](int st, int k0) {
#pragma unroll
        for (int p = 0; p < 2; ++p) {
            int q = tid + 256 * p;
            int row = q >> 2, cik = q & 3;
            int c = k0 + cik * 8;
            int r = row0 + row;
            const __half* asrc = A;
            int sz = 0;
            if (r < M) {
                sz = 16;
                if (SPLITA) asrc = (c < HIDN) ? (A + (size_t)r * HIDN + c)
                                              : (A2 + (size_t)r * HIDN + (c - HIDN));
                else        asrc = A + (size_t)r * K + c;
            }
            cp16((uint32_t)__cvta_generic_to_shared(AsB + st * MM_TILE_U32 + row * 20 + cik * 4),
                 asrc, sz);
            const __half* bsrc = Bt + (size_t)(col0 + row) * K + c;
            cp16((uint32_t)__cvta_generic_to_shared(BsB + st * MM_TILE_U32 + row * 20 + cik * 4),
                 bsrc, 16);
        }
        cp_commit();
    };

    const uint32_t a_lane_off = ((lane & 7) + 8 * ((lane >> 3) & 1)) * 80 + 16 * (lane >> 4);
    const uint32_t b_lane_off = ((lane & 7) + 8 * (lane >> 4)) * 80 + 16 * ((lane >> 3) & 1);

    const int nIter = K / 32;
    issue(0, 0);
    issue(1, 32);
    for (int it = 0; it < nIter; ++it) {
        if (it == nIter - 1) cp_wait<0>(); else cp_wait<1>();
        __syncthreads();
        if (it + 2 < nIter) issue((it + 2) % MM_STAGES, (it + 2) * 32);
        const uint32_t As_byte =
            (uint32_t)__cvta_generic_to_shared(AsB + (it % MM_STAGES) * MM_TILE_U32);
        const uint32_t Bs_byte =
            (uint32_t)__cvta_generic_to_shared(BsB + (it % MM_STAGES) * MM_TILE_U32);
#pragma unroll
        for (int ks = 0; ks < 2; ++ks) {
            uint32_t af[4][4], bf[4][2];
#pragma unroll
            for (int mi = 0; mi < 4; ++mi)
                ldsm_x4(af[mi][0], af[mi][1], af[mi][2], af[mi][3],
                        As_byte + (warp_m + 16 * mi) * 80 + ks * 32 + a_lane_off);
#pragma unroll
            for (int np = 0; np < 2; ++np)
                ldsm_x4(bf[2 * np][0], bf[2 * np][1], bf[2 * np + 1][0], bf[2 * np + 1][1],
                        Bs_byte + (warp_n + 16 * np) * 80 + ks * 32 + b_lane_off);
#pragma unroll
            for (int mi = 0; mi < 4; ++mi)
#pragma unroll
                for (int ni = 0; ni < 4; ++ni)
                    mma_f16(acc[mi][ni], af[mi], bf[ni]);
        }
    }

#pragma unroll
    for (int mi = 0; mi < 4; ++mi) {
#pragma unroll
        for (int ni = 0; ni < 4; ++ni) {
            int rA = row0 + warp_m + 16 * mi + g;
            int cA = col0 + warp_n + 8 * ni + 2 * tig;
#pragma unroll
            for (int half_ = 0; half_ < 2; ++half_) {
                int r = rA + half_ * 8;
                if (r >= M) continue;
                float v0 = acc[mi][ni][half_ * 2 + 0];
                float v1 = acc[mi][ni][half_ * 2 + 1];
                if (EPI == 2) {
                    v0 = fmaxf(v0 + add[(size_t)r * N + cA + 0], 0.0f);
                    v1 = fmaxf(v1 + add[(size_t)r * N + cA + 1], 0.0f);
                } else if (EPI == 3) {
                    v0 = fmaxf(v0 + bias[cA + 0], 0.0f);
                    v1 = fmaxf(v1 + bias[cA + 1], 0.0f);
                }
                __half2* C = (__half2*)Cout;
                C[((size_t)r * N + cA) >> 1] = __floats2half2_rn(v0, v1);
            }
        }
    }
}

// ---------------- host launch ----------------
static inline int cdiv(int a, int b) { return (a + b - 1) / b; }

extern "C" void kernel_launch(void* const* d_in, const int* in_sizes, int n_in,
                              void* d_out, int out_size) {
    (void)in_sizes; (void)n_in; (void)out_size;
    const float* x_link  = (const float*)d_in[0];
    const float* x_flow  = (const float*)d_in[1];
    const float* x_path  = (const float*)d_in[2];
    const float* e2p     = (const float*)d_in[3];
    const float* Wp_link = (const float*)d_in[4];
    const float* bp_link = (const float*)d_in[5];
    const float* Wp_flow = (const float*)d_in[6];
    const float* bp_flow = (const float*)d_in[7];
    const float* Wp_path = (const float*)d_in[8];
    const float* bp_path = (const float*)d_in[9];
    const float* fc_src1 = (const float*)d_in[10];
    const float* fc_dst1 = (const float*)d_in[11];
    const float* fc_e1   = (const float*)d_in[12];
    const float* attn_l1 = (const float*)d_in[13];
    const float* attn_r1 = (const float*)d_in[14];
    const float* attn_e1 = (const float*)d_in[15];
    const float* res_W1  = (const float*)d_in[16];
    const float* fc_src2 = (const float*)d_in[17];
    const float* fc_dst2 = (const float*)d_in[18];
    const float* attn_l2 = (const float*)d_in[19];
    const float* attn_r2 = (const float*)d_in[20];
    const float* res_W2  = (const float*)d_in[21];
    const float* W1      = (const float*)d_in[22];
    const float* b1      = (const float*)d_in[23];
    const float* W2      = (const float*)d_in[24];
    const float* b2      = (const float*)d_in[25];
    const int*   src1    = (const int*)d_in[26];
    const int*   dst1    = (const int*)d_in[27];
    const int*   src2    = (const int*)d_in[28];
    const int*   dst2    = (const int*)d_in[29];
    float* out = (float*)d_out;

#define SYMF(p, s) float* p; cudaGetSymbolAddress((void**)&p, s)
#define SYMH(p, s) __half* p; cudaGetSymbolAddress((void**)&p, s)
    SYMH(p_hlink, g_h_link);  SYMH(p_hflow, g_h_flow);
    SYMH(p_hp0, g_h_path0);   SYMH(p_hp1, g_h_path1);   SYMH(p_hp2, g_h_path2);
    SYMH(p_zs1, g_zs1);       SYMH(p_zs2, g_zs2);       SYMH(p_hidden, g_hidden);
    SYMF(p_el1, g_el1);       SYMF(p_er1, g_er1);
    SYMF(p_el2, g_el2);       SYMF(p_er2, g_er2);
    SYMF(p_ea1, g_ea1);       SYMF(p_ea2, g_ea2);
    SYMF(p_denom1, g_denom1); SYMF(p_denom2, g_denom2);
    SYMF(p_agg1, g_agg1);     SYMF(p_agg2, g_agg2);
    SYMF(p_wl1, g_wl1);       SYMF(p_wr1, g_wr1);
    SYMF(p_wl2, g_wl2);       SYMF(p_wr2, g_wr2);       SYMF(p_ce, g_ce);
    SYMH(p_fc1t, g_fc1t);     SYMH(p_fc2t, g_fc2t);
    SYMH(p_rw1t, g_rw1t);     SYMH(p_rw2t, g_rw2t);     SYMH(p_wcatT, g_wcatT);
#undef SYMF
#undef SYMH

    const int T = 256;

    // one-time host-object setup (host objects only; no device memory)
    static cudaStream_t s2 = nullptr, s3 = nullptr;
    static cudaEvent_t evW = nullptr, evA = nullptr, evF = nullptr, evP = nullptr, evJ2 = nullptr;
    if (s2 == nullptr) {
        cudaStreamCreateWithFlags(&s2, cudaStreamNonBlocking);
        cudaStreamCreateWithFlags(&s3, cudaStreamNonBlocking);
        cudaEventCreateWithFlags(&evW, cudaEventDisableTiming);
        cudaEventCreateWithFlags(&evA, cudaEventDisableTiming);
        cudaEventCreateWithFlags(&evF, cudaEventDisableTiming);
        cudaEventCreateWithFlags(&evP, cudaEventDisableTiming);
        cudaEventCreateWithFlags(&evJ2, cudaEventDisableTiming);
        cudaFuncSetAttribute(mm_f16<1, false>, cudaFuncAttributeMaxDynamicSharedMemorySize, MM_SMEM_BYTES);
        cudaFuncSetAttribute(mm_f16<2, false>, cudaFuncAttributeMaxDynamicSharedMemorySize, MM_SMEM_BYTES);
        cudaFuncSetAttribute(mm_f16<3, true>,  cudaFuncAttributeMaxDynamicSharedMemorySize, MM_SMEM_BYTES);
    }

    // root fork: side streams branch off the capture origin
    static cudaEvent_t evRoot = nullptr;
    if (evRoot == nullptr) cudaEventCreateWithFlags(&evRoot, cudaEventDisableTiming);
    cudaEventRecord(evRoot, 0);
    cudaStreamWaitEvent(s2, evRoot, 0);
    cudaStreamWaitEvent(s3, evRoot, 0);

    // ---- s2: weight prep, then zs2 GEMM (after flow proj) ----
    prep_weights<<<cdiv(1024 * 256, T), T, 0, s2>>>(fc_src1, fc_src2, res_W1, res_W2, W1,
                                                    p_fc1t, p_fc2t, p_rw1t, p_rw2t, p_wcatT);
    cudaEventRecord(evW, s2);

    // ---- s3: attn folded weights + both conv-state fills ----
    attn_reduce_all<<<cdiv(4100 * 32, T), T, 0, s3>>>(
        fc_src1, attn_l1, p_wl1,  fc_dst1, attn_r1, p_wr1,
        fc_src2, attn_l2, p_wl2,  fc_dst2, attn_r2, p_wr2,
        fc_e1, attn_e1, p_ce);
    cudaEventRecord(evA, s3);
    fill_conv_state<<<cdiv(NPATH * HIDN, T), T, 0, s3>>>(p_denom1, p_agg1);
    fill_conv_state<<<cdiv(NPATH * HIDN, T), T, 0, s3>>>(p_denom2, p_agg2);
    cudaEventRecord(evF, s3);

    // ---- main: node projections ----
    proj_relu<8><<<cdiv(NLINK, 32), T>>>(x_link, Wp_link, bp_link, p_hlink, NLINK);
    proj_relu<16><<<cdiv(NFLOW, 32), T>>>(x_flow, Wp_flow, bp_flow, p_hflow, NFLOW);
    cudaEventRecord(evP, 0);   // hflow ready
    proj_relu<8><<<cdiv(NPATH, 32), T>>>(x_path, Wp_path, bp_path, p_hp0, NPATH);

    // ---- s2: zs2 GEMM (needs hflow + fc2t) ----
    cudaStreamWaitEvent(s2, evP, 0);
    {
        dim3 g2(1024 / 128, cdiv(NFLOW, 128));
        mm_f16<1, false><<<g2, T, MM_SMEM_BYTES, s2>>>(p_hflow, nullptr, p_fc2t, p_zs2,
                                                       NFLOW, 1024, 256, nullptr, nullptr);
    }
    cudaEventRecord(evJ2, s2);

    // ---- main: zs1 GEMM (needs fc1t from s2) ----
    cudaStreamWaitEvent(0, evW, 0);
    {
        dim3 g1(1024 / 128, cdiv(NLINK, 128));
        mm_f16<1, false><<<g1, T, MM_SMEM_BYTES>>>(p_hlink, nullptr, p_fc1t, p_zs1,
                                                   NLINK, 1024, 256, nullptr, nullptr);
    }

    // ---- attn scores (needs wl/wr from s3) ----
    cudaStreamWaitEvent(0, evA, 0);
    attn_score3<<<cdiv((NLINK + NFLOW + NPATH) * 32, T), T>>>(
        p_hlink, p_hflow, p_hp0, p_wl1, p_wl2, p_wr1, p_el1, p_el2, p_er1);

    // ================= conv 1 =================
    cudaStreamWaitEvent(0, evF, 0);   // fills done (joins s3)
    edge_softmax<true><<<cdiv(E1N, T), T>>>(p_el1, p_er1, e2p, p_ce, src1, dst1,
                                            p_ea1, p_denom1, E1N);
    edge_scatter<<<cdiv(E1N, 8), 512>>>(p_zs1, p_ea1, p_denom1, src1, dst1, p_agg1, E1N);
    {
        dim3 g(HIDN / 128, cdiv(NPATH, 128));
        mm_f16<2, false><<<g, T, MM_SMEM_BYTES>>>(p_hp0, nullptr, p_rw1t, p_hp1,
                                                  NPATH, HIDN, 256, p_agg1, nullptr);
    }

    // ================= conv 2 =================
    attn_score1<<<cdiv(NPATH * 32, T), T>>>(p_hp1, p_wr2, p_er2, NPATH);
    edge_softmax<false><<<cdiv(E2N, T), T>>>(p_el2, p_er2, nullptr, nullptr, src2, dst2,
                                             p_ea2, p_denom2, E2N);
    cudaStreamWaitEvent(0, evJ2, 0);   // zs2 ready (joins s2)
    edge_scatter<<<cdiv(E2N, 8), 512>>>(p_zs2, p_ea2, p_denom2, src2, dst2, p_agg2, E2N);
    {
        dim3 g(HIDN / 128, cdiv(NPATH, 128));
        mm_f16<2, false><<<g, T, MM_SMEM_BYTES>>>(p_hp1, nullptr, p_rw2t, p_hp2,
                                                  NPATH, HIDN, 256, p_agg2, nullptr);
    }

    // ================= decoder =================
    {
        dim3 g(HIDN / 128, cdiv(NPATH, 128));
        mm_f16<3, true><<<g, T, MM_SMEM_BYTES>>>(p_hp2, p_hp1, p_wcatT, p_hidden,
                                                 NPATH, HIDN, 512, nullptr, b1);
    }
    decoder_out<<<cdiv(NPATH * 32, T), T>>>(p_hidden, W2, b2, out);
}